// round 10
// baseline (speedup 1.0000x reference)
#include <cuda_runtime.h>

// ---------------------------------------------------------------------------
// NCF_Feature: split structure.
//  k_main: bag (2x-unrolled, __ldcs streaming) + GEMVs + one-hot + BN partials;
//          LAST block computes scale/shift. Feat written COLUMN-MAJOR.
//  k_mlp : 4 sub-lanes per row, ILP-4 layer-1 accumulators, full-chip grid.
// ---------------------------------------------------------------------------

#define B_ROWS 16384
#define TAGS   4096
#define GMAIN  256            // k_main blocks; 64 rows per block
#define NWARP  16             // warps per k_main block (512 threads)

// Scratch (allocation-free rule: __device__ globals)
__device__ float g_featT[32 * (size_t)B_ROWS];  // column-major: [col][row]
__device__ float g_part[GMAIN * 40];            // per-block: sum[20], sumsq[20]
__device__ float g_scale[20];
__device__ float g_shift[20];
__device__ unsigned int g_arrive;               // zero-init; self-resetting

__device__ __forceinline__ float warpsum(float v) {
#pragma unroll
    for (int o = 16; o; o >>= 1) v += __shfl_xor_sync(0xffffffffu, v, o);
    return v;
}

// ===========================================================================
// Kernel 1: HBM streamer. 512 threads, 2 CTA/SM.
// ===========================================================================
__global__ void __launch_bounds__(512, 2)
k_main(const float* __restrict__ uf_g, const float* __restrict__ if_g,
       const float* __restrict__ ut_g, const float* __restrict__ it_g,
       const float* __restrict__ Wu,   const float* __restrict__ bu,
       const float* __restrict__ Wi,   const float* __restrict__ bi,
       const float* __restrict__ Eu,   const float* __restrict__ Ei,
       const float* __restrict__ g1,   const float* __restrict__ be1,
       const float* __restrict__ g2,   const float* __restrict__ be2)
{
    extern __shared__ float sm[];
    float* sE   = sm;                 // 5*4096 SoA
    float* sWu  = sm + 20480;         // 10*128
    float* sWi  = sm + 21760;         // 10*128
    float* sRed = sm + 23040;         // NWARP*40

    const int tid = threadIdx.x;

    for (int i = tid; i < TAGS; i += 512) {
        float e0 = Ei[i * 5 + 0], e1 = Ei[i * 5 + 1], e2 = Ei[i * 5 + 2];
        float e3 = Ei[i * 5 + 3], e4 = Ei[i * 5 + 4];
        sE[0 * TAGS + i] = e0; sE[1 * TAGS + i] = e1; sE[2 * TAGS + i] = e2;
        sE[3 * TAGS + i] = e3; sE[4 * TAGS + i] = e4;
    }
    for (int i = tid; i < 1280; i += 512) { sWu[i] = Wu[i]; sWi[i] = Wi[i]; }
    __syncthreads();

    const int warp = tid >> 5, lane = tid & 31;
    const int rowbase = blockIdx.x * 64 + warp * 4;
    const float4* sE4  = (const float4*)sE;
    const float4* sWu4 = (const float4*)sWu;
    const float4* sWi4 = (const float4*)sWi;

    float su = 0.f, sq = 0.f;

#pragma unroll 1
    for (int q = 0; q < 2; q++) {
        const int r0 = rowbase + q * 2;

        // ---- weighted tag bag: 2 rows, 2x unrolled, streaming loads ----
        const float4* t0 = (const float4*)(ut_g + (size_t)(r0 + 0) * TAGS);
        const float4* t1 = (const float4*)(ut_g + (size_t)(r0 + 1) * TAGS);
        float acc0[5], acc1[5];
#pragma unroll
        for (int k = 0; k < 5; k++) { acc0[k] = 0.f; acc1[k] = 0.f; }

#pragma unroll 1
        for (int i = lane; i < TAGS / 4; i += 64) {
            float4 a0 = __ldcs(t0 + i);
            float4 a1 = __ldcs(t1 + i);
            float4 b0 = __ldcs(t0 + i + 32);
            float4 b1 = __ldcs(t1 + i + 32);
            float4 ee;
#pragma unroll
            for (int k = 0; k < 5; k++) {
                ee = sE4[k * (TAGS / 4) + i];
                acc0[k] += a0.x * ee.x + a0.y * ee.y + a0.z * ee.z + a0.w * ee.w;
                acc1[k] += a1.x * ee.x + a1.y * ee.y + a1.z * ee.z + a1.w * ee.w;
            }
#pragma unroll
            for (int k = 0; k < 5; k++) {
                ee = sE4[k * (TAGS / 4) + i + 32];
                acc0[k] += b0.x * ee.x + b0.y * ee.y + b0.z * ee.z + b0.w * ee.w;
                acc1[k] += b1.x * ee.x + b1.y * ee.y + b1.z * ee.z + b1.w * ee.w;
            }
        }
#pragma unroll
        for (int k = 0; k < 5; k++) {
            float s0 = warpsum(acc0[k]) * 0.1f;
            float s1 = warpsum(acc1[k]) * 0.1f;
            if (lane == k) {
                g_featT[(10 + k) * (size_t)B_ROWS + (r0 + 0)] = s0;
                g_featT[(10 + k) * (size_t)B_ROWS + (r0 + 1)] = s1;
            }
        }

        // ---- per-row: GEMVs + one-hot search ----
#pragma unroll 1
        for (int r = 0; r < 2; r++) {
            const int rr = r0 + r;
            const float4* it4 = (const float4*)(it_g + (size_t)rr * TAGS);

            float4 v[8];
#pragma unroll
            for (int k = 0; k < 8; k++) v[k] = __ldcs(it4 + k * 32 + lane);

            float4 xu = ((const float4*)(uf_g + (size_t)rr * 128))[lane];
            float4 xi = ((const float4*)(if_g + (size_t)rr * 128))[lane];
#pragma unroll
            for (int j = 0; j < 10; j++) {
                float4 wu = sWu4[j * 32 + lane];
                float s = warpsum(xu.x * wu.x + xu.y * wu.y + xu.z * wu.z + xu.w * wu.w) + bu[j];
                if (lane == j) { g_featT[j * (size_t)B_ROWS + rr] = s; su += s; sq += s * s; }
                float4 wi = sWi4[j * 32 + lane];
                float s2 = warpsum(xi.x * wi.x + xi.y * wi.y + xi.z * wi.z + xi.w * wi.w) + bi[j];
                if (lane == j + 10) { g_featT[(15 + j) * (size_t)B_ROWS + rr] = s2; su += s2; sq += s2 * s2; }
            }

            int hot = 0;
#pragma unroll 1
            for (int base = 0; base < 1024; base += 256) {
                int m = 0;
#pragma unroll
                for (int k = 0; k < 8; k++) {
                    m |= (v[k].x == 1.f) << (k * 4 + 0);
                    m |= (v[k].y == 1.f) << (k * 4 + 1);
                    m |= (v[k].z == 1.f) << (k * 4 + 2);
                    m |= (v[k].w == 1.f) << (k * 4 + 3);
                }
                unsigned bal = __ballot_sync(0xffffffffu, m != 0);
                if (bal) {
                    int src = __ffs(bal) - 1;
                    int mm  = __shfl_sync(0xffffffffu, m, src);
                    int bit = __ffs(mm) - 1;
                    hot = 4 * (base + (bit >> 2) * 32 + src) + (bit & 3);
                    break;
                }
                if (base + 256 < 1024) {
#pragma unroll
                    for (int k = 0; k < 8; k++) v[k] = __ldcs(it4 + base + 256 + k * 32 + lane);
                }
            }
            if (lane < 5) g_featT[(25 + lane) * (size_t)B_ROWS + rr] = Eu[(size_t)hot * 5 + lane];
        }
    }

    // ---- per-block BN partials -> g_part ----
    if (lane < 20) { sRed[warp * 40 + lane] = su; sRed[warp * 40 + 20 + lane] = sq; }
    __syncthreads();
    if (tid < 40) {
        float s = 0.f;
#pragma unroll
        for (int w = 0; w < NWARP; w++) s += sRed[w * 40 + tid];
        g_part[blockIdx.x * 40 + tid] = s;
    }

    // ---- last-arriving block computes BN scale/shift ----
    __threadfence();
    __syncthreads();
    __shared__ int sLast;
    if (tid == 0) sLast = (atomicAdd(&g_arrive, 1u) == GMAIN - 1);
    __syncthreads();
    if (sLast) {
        const int j = tid % 40, g = tid / 40;
        if (tid < 320) {
            float s = 0.f;
#pragma unroll 4
            for (int i = 0; i < 32; i++) s += g_part[(g * 32 + i) * 40 + j];
            sRed[g * 40 + j] = s;
        }
        __syncthreads();
        if (tid < 20) {
            float s0 = 0.f, s1 = 0.f;
#pragma unroll
            for (int gg = 0; gg < 8; gg++) { s0 += sRed[gg * 40 + tid]; s1 += sRed[gg * 40 + 20 + tid]; }
            float mean = s0 * (1.f / B_ROWS);
            float var  = s1 * (1.f / B_ROWS) - mean * mean;   // biased
            float ga = (tid < 10) ? g1[tid]  : g2[tid - 10];
            float be = (tid < 10) ? be1[tid] : be2[tid - 10];
            float sc = ga * rsqrtf(var + 1e-5f);
            g_scale[tid] = sc;
            g_shift[tid] = be - mean * sc;
        }
        __syncthreads();
        if (tid == 0) { g_arrive = 0u; __threadfence(); }
    }
}

// ===========================================================================
// Kernel 2: 4 sub-lanes per row; layer-1 uses 4 independent accumulators
// (chain depth 8, not 32). 256 blocks x 256 threads -> all SMs, 2 CTA/SM.
// ===========================================================================
__global__ void __launch_bounds__(256)
k_mlp(const float* __restrict__ W1, const float* __restrict__ b1,
      const float* __restrict__ W2, const float* __restrict__ b2,
      const float* __restrict__ W3, const float* __restrict__ b3,
      float* __restrict__ out)
{
    __shared__ float sW1[64 * 32];      // [o][i], i padded 30->32 with zeros
    __shared__ float sW2T[64 * 32];     // [o][j] (transposed W2)
    __shared__ float sb1[64];
    __shared__ float sb2[32];
    __shared__ float sW3[32];
    __shared__ float csc[32], csh[32];
    __shared__ float sb3;

    const int tid = threadIdx.x;
    for (int i = tid; i < 64 * 32; i += 256) sW1[i] = 0.f;
    __syncthreads();
    for (int i = tid; i < 1920; i += 256) sW1[(i / 30) * 32 + (i % 30)] = W1[i];
    for (int i = tid; i < 2048; i += 256) sW2T[(i % 64) * 32 + (i / 64)] = W2[i];
    if (tid < 64) sb1[tid] = b1[tid];
    if (tid < 32) { sb2[tid] = b2[tid]; sW3[tid] = W3[tid]; }
    if (tid < 32) {
        int c = tid;
        bool bn = (c < 10) || (c >= 15 && c < 25);
        int sj = (c < 10) ? c : c - 5;
        csc[c] = bn ? g_scale[sj] : 1.f;
        csh[c] = bn ? g_shift[sj] : 0.f;
    }
    if (tid == 0) sb3 = b3[0];
    __syncthreads();

    const int warp = tid >> 5, lane = tid & 31;
    const int sub = lane >> 3, r = lane & 7;
    const int row = blockIdx.x * 64 + warp * 8 + r;

    float x[32];
#pragma unroll
    for (int i = 0; i < 30; i++)
        x[i] = g_featT[i * (size_t)B_ROWS + row] * csc[i] + csh[i];
    x[30] = 0.f; x[31] = 0.f;

    float h2[32];
#pragma unroll
    for (int j = 0; j < 32; j++) h2[j] = (sub == 0) ? sb2[j] : 0.f;

    const float4* w1v = (const float4*)sW1;
    const float4* w2v = (const float4*)sW2T;
    const int ob = sub * 16;

#pragma unroll
    for (int oo = 0; oo < 16; oo++) {
        const int o = ob + oo;
        // 4 independent accumulators: dependency chain depth 8 instead of 32
        float4 wa = w1v[o * 8 + 0], wb = w1v[o * 8 + 1];
        float4 wc = w1v[o * 8 + 2], wd = w1v[o * 8 + 3];
        float4 we = w1v[o * 8 + 4], wf = w1v[o * 8 + 5];
        float4 wg = w1v[o * 8 + 6], wh = w1v[o * 8 + 7];
        float ta = wa.x * x[0]  + wa.y * x[1]  + wa.z * x[2]  + wa.w * x[3]
                 + wb.x * x[4]  + wb.y * x[5]  + wb.z * x[6]  + wb.w * x[7];
        float tb = wc.x * x[8]  + wc.y * x[9]  + wc.z * x[10] + wc.w * x[11]
                 + wd.x * x[12] + wd.y * x[13] + wd.z * x[14] + wd.w * x[15];
        float tc = we.x * x[16] + we.y * x[17] + we.z * x[18] + we.w * x[19]
                 + wf.x * x[20] + wf.y * x[21] + wf.z * x[22] + wf.w * x[23];
        float td = wg.x * x[24] + wg.y * x[25] + wg.z * x[26] + wg.w * x[27]
                 + wh.x * x[28] + wh.y * x[29] + wh.z * x[30] + wh.w * x[31];
        float t = fmaxf(sb1[o] + (ta + tb) + (tc + td), 0.f);
#pragma unroll
        for (int j4 = 0; j4 < 8; j4++) {
            float4 w = w2v[o * 8 + j4];
            h2[j4 * 4 + 0] += w.x * t;
            h2[j4 * 4 + 1] += w.y * t;
            h2[j4 * 4 + 2] += w.z * t;
            h2[j4 * 4 + 3] += w.w * t;
        }
    }

    // reduce partial h2 across the 4 subs of this row
#pragma unroll
    for (int j = 0; j < 32; j++) {
        h2[j] += __shfl_xor_sync(0xffffffffu, h2[j], 8);
        h2[j] += __shfl_xor_sync(0xffffffffu, h2[j], 16);
    }

    float s = sb3;
    const float4* w3v = (const float4*)sW3;
#pragma unroll
    for (int j4 = 0; j4 < 8; j4++) {
        float4 w = w3v[j4];
        s += w.x * fmaxf(h2[j4 * 4 + 0], 0.f)
           + w.y * fmaxf(h2[j4 * 4 + 1], 0.f)
           + w.z * fmaxf(h2[j4 * 4 + 2], 0.f)
           + w.w * fmaxf(h2[j4 * 4 + 3], 0.f);
    }
    if (sub == 0) out[row] = fmaxf(s, 0.f);
}

// ===========================================================================
extern "C" void kernel_launch(void* const* d_in, const int* in_sizes, int n_in,
                              void* d_out, int out_size)
{
    (void)in_sizes; (void)n_in; (void)out_size;
    const float* user_feature = (const float*)d_in[2];
    const float* item_feature = (const float*)d_in[3];
    const float* user_tag     = (const float*)d_in[4];
    const float* item_tag     = (const float*)d_in[5];
    const float* W_user = (const float*)d_in[6];
    const float* b_user = (const float*)d_in[7];
    const float* W_item = (const float*)d_in[8];
    const float* b_item = (const float*)d_in[9];
    const float* E_user_tag = (const float*)d_in[10];
    const float* E_item_tag = (const float*)d_in[11];
    const float* g1  = (const float*)d_in[12];
    const float* be1 = (const float*)d_in[13];
    const float* g2  = (const float*)d_in[14];
    const float* be2 = (const float*)d_in[15];
    const float* W1 = (const float*)d_in[16];
    const float* b1 = (const float*)d_in[17];
    const float* W2 = (const float*)d_in[18];
    const float* b2 = (const float*)d_in[19];
    const float* W3 = (const float*)d_in[20];
    const float* b3 = (const float*)d_in[21];

    const int smem_bytes = (23040 + NWARP * 40) * (int)sizeof(float);  // 94,720 B
    cudaFuncSetAttribute(k_main, cudaFuncAttributeMaxDynamicSharedMemorySize, smem_bytes);

    k_main<<<GMAIN, 512, smem_bytes>>>(user_feature, item_feature, user_tag, item_tag,
                                       W_user, b_user, W_item, b_item,
                                       E_user_tag, E_item_tag,
                                       g1, be1, g2, be2);
    k_mlp<<<256, 256>>>(W1, b1, W2, b2, W3, b3, (float*)d_out);
}